// round 1
// baseline (speedup 1.0000x reference)
#include <cuda_runtime.h>
#include <cuda_bf16.h>
#include <math.h>

// Problem constants: B=2, S=2048, D=2048, H=16, hd=128
#define SEQ     2048
#define D_MODEL 2048
#define NHEAD   16
#define HD      128
#define BATCH   2

#define FBQ 64
#define FBK 64
#define QPITCH 68   // 64 + 4 pad (keeps float4 alignment, breaks bank stride)

// Scratch (allocation-free rule: __device__ globals)
__device__ float g_q[BATCH * SEQ * D_MODEL];
__device__ float g_k[BATCH * SEQ * D_MODEL];
__device__ float g_v[BATCH * SEQ * D_MODEL];
__device__ float g_attn[BATCH * SEQ * D_MODEL];

// ---------------------------------------------------------------------------
// SGEMM NT: C[M,N] = A[M,K] @ B[N,K]^T  (both row-major, K contiguous)
// 128x128 block tile, BK=16, 256 threads, 8x8 microtile.
// ---------------------------------------------------------------------------
__global__ __launch_bounds__(256, 2)
void sgemm_nt(const float* __restrict__ A, const float* __restrict__ B,
              float* __restrict__ C, int M, int N, int K)
{
    __shared__ float As[16][128];
    __shared__ float Bs[16][128];

    const int tid = threadIdx.x;
    const int tr = tid >> 4;      // 0..15
    const int tc = tid & 15;      // 0..15
    const int brow = blockIdx.y * 128;
    const int bcol = blockIdx.x * 128;
    const int lr = tid >> 2;      // 0..63
    const int lc = tid & 3;       // 0..3 (float4 group)

    const float* Ab = A + (size_t)brow * K;
    const float* Bb = B + (size_t)bcol * K;

    float acc[8][8];
#pragma unroll
    for (int i = 0; i < 8; i++)
#pragma unroll
        for (int j = 0; j < 8; j++) acc[i][j] = 0.0f;

    for (int k0 = 0; k0 < K; k0 += 16) {
#pragma unroll
        for (int rr = 0; rr < 2; rr++) {
            int r = lr + rr * 64;
            float4 a4 = *(const float4*)(Ab + (size_t)r * K + k0 + lc * 4);
            As[lc * 4 + 0][r] = a4.x;
            As[lc * 4 + 1][r] = a4.y;
            As[lc * 4 + 2][r] = a4.z;
            As[lc * 4 + 3][r] = a4.w;
            float4 b4 = *(const float4*)(Bb + (size_t)r * K + k0 + lc * 4);
            Bs[lc * 4 + 0][r] = b4.x;
            Bs[lc * 4 + 1][r] = b4.y;
            Bs[lc * 4 + 2][r] = b4.z;
            Bs[lc * 4 + 3][r] = b4.w;
        }
        __syncthreads();

#pragma unroll
        for (int k = 0; k < 16; k++) {
            float4 a0 = *(const float4*)&As[k][tr * 8];
            float4 a1 = *(const float4*)&As[k][tr * 8 + 4];
            float4 b0 = *(const float4*)&Bs[k][tc * 8];
            float4 b1 = *(const float4*)&Bs[k][tc * 8 + 4];
            float am[8] = {a0.x, a0.y, a0.z, a0.w, a1.x, a1.y, a1.z, a1.w};
            float bn[8] = {b0.x, b0.y, b0.z, b0.w, b1.x, b1.y, b1.z, b1.w};
#pragma unroll
            for (int i = 0; i < 8; i++)
#pragma unroll
                for (int j = 0; j < 8; j++)
                    acc[i][j] = fmaf(am[i], bn[j], acc[i][j]);
        }
        __syncthreads();
    }

#pragma unroll
    for (int i = 0; i < 8; i++) {
        float* cp = C + (size_t)(brow + tr * 8 + i) * N + bcol + tc * 8;
        float4 c0 = {acc[i][0], acc[i][1], acc[i][2], acc[i][3]};
        float4 c1 = {acc[i][4], acc[i][5], acc[i][6], acc[i][7]};
        *(float4*)cp = c0;
        *(float4*)(cp + 4) = c1;
    }
}

// ---------------------------------------------------------------------------
// RoPE in-place on [B,S,D] with heads packed (interleaved pairs).
// inv_freq computed in fp64 then rounded -> matches jax f32 within ~1 ulp.
// ---------------------------------------------------------------------------
__global__ void rope_kernel(float* __restrict__ Y, int total_pairs)
{
    int p = blockIdx.x * blockDim.x + threadIdx.x;
    if (p >= total_pairs) return;
    int pair = p & 63;                 // 0..63 within head
    int h    = (p >> 6) & (NHEAD - 1);
    int s    = (p >> 10) & (SEQ - 1);
    int b    = p >> 21;

    // inv_freq = 10000^(-(2*pair)/128) = exp(-(pair/64)*ln(10000))
    float inv = (float)exp(-(double)pair * (9.210340371976184 / 64.0));
    float ang = (float)s * inv;
    float sn, cs;
    sincosf(ang, &sn, &cs);

    size_t off = ((size_t)(b * SEQ + s)) * D_MODEL + h * HD + pair * 2;
    float2 v = *(float2*)(Y + off);
    float2 r;
    r.x = v.x * cs - v.y * sn;
    r.y = v.x * sn + v.y * cs;
    *(float2*)(Y + off) = r;
}

// ---------------------------------------------------------------------------
// Flash attention, fp32, causal. BQ=BK=64, hd=128, 256 threads (16x16).
// Q/K staged d-major (transposed) in smem; V natural; P transposed via smem.
// Output written straight into [B,S,D] packed-head layout.
// ---------------------------------------------------------------------------
__global__ __launch_bounds__(256)
void flash_attn(const float* __restrict__ Q, const float* __restrict__ K,
                const float* __restrict__ V, float* __restrict__ Oout)
{
    extern __shared__ float sm[];
    float* Qs = sm;                        // [HD][QPITCH]
    float* Ks = Qs + HD * QPITCH;          // [HD][QPITCH]
    float* Vs = Ks + HD * QPITCH;          // [FBK][HD]
    float* Ps = Vs + FBK * HD;             // [FBK][QPITCH]

    const int qt = blockIdx.x;
    const int bh = blockIdx.y;
    const int b = bh >> 4, h = bh & 15;
    const int q0 = qt * FBQ;
    const int tid = threadIdx.x;
    const int tx = tid & 15, ty = tid >> 4;

    const float* Qb = Q + ((size_t)b * SEQ) * D_MODEL + h * HD;
    const float* Kb = K + ((size_t)b * SEQ) * D_MODEL + h * HD;
    const float* Vb = V + ((size_t)b * SEQ) * D_MODEL + h * HD;

    // Load Q tile transposed: Qs[d][m]
    for (int idx = tid; idx < FBQ * 32; idx += 256) {
        int r = idx >> 5;
        int c4 = (idx & 31) * 4;
        float4 v4 = *(const float4*)(Qb + (size_t)(q0 + r) * D_MODEL + c4);
        Qs[(c4 + 0) * QPITCH + r] = v4.x;
        Qs[(c4 + 1) * QPITCH + r] = v4.y;
        Qs[(c4 + 2) * QPITCH + r] = v4.z;
        Qs[(c4 + 3) * QPITCH + r] = v4.w;
    }

    float o[4][8];
#pragma unroll
    for (int i = 0; i < 4; i++)
#pragma unroll
        for (int j = 0; j < 8; j++) o[i][j] = 0.0f;
    float rm[4], rl[4];
#pragma unroll
    for (int i = 0; i < 4; i++) { rm[i] = -1e30f; rl[i] = 0.0f; }

    const float scale = 0.08838834764831845f;   // 1/sqrt(128)
    const int ntiles = qt + 1;                  // causal

    for (int t = 0; t < ntiles; t++) {
        int k0 = t * FBK;
        __syncthreads();   // Qs ready (t=0) / previous PV done (t>0)

        for (int idx = tid; idx < FBK * 32; idx += 256) {
            int r = idx >> 5;
            int c4 = (idx & 31) * 4;
            float4 kv = *(const float4*)(Kb + (size_t)(k0 + r) * D_MODEL + c4);
            Ks[(c4 + 0) * QPITCH + r] = kv.x;
            Ks[(c4 + 1) * QPITCH + r] = kv.y;
            Ks[(c4 + 2) * QPITCH + r] = kv.z;
            Ks[(c4 + 3) * QPITCH + r] = kv.w;
            float4 vv = *(const float4*)(Vb + (size_t)(k0 + r) * D_MODEL + c4);
            *(float4*)&Vs[r * HD + c4] = vv;
        }
        __syncthreads();

        // S = Q @ K^T (4x4 microtile)
        float s[4][4];
#pragma unroll
        for (int i = 0; i < 4; i++)
#pragma unroll
            for (int j = 0; j < 4; j++) s[i][j] = 0.0f;

#pragma unroll 4
        for (int k = 0; k < HD; k++) {
            float4 qa = *(const float4*)&Qs[k * QPITCH + ty * 4];
            float4 ka = *(const float4*)&Ks[k * QPITCH + tx * 4];
            float qv[4] = {qa.x, qa.y, qa.z, qa.w};
            float kv[4] = {ka.x, ka.y, ka.z, ka.w};
#pragma unroll
            for (int i = 0; i < 4; i++)
#pragma unroll
                for (int j = 0; j < 4; j++)
                    s[i][j] = fmaf(qv[i], kv[j], s[i][j]);
        }

#pragma unroll
        for (int i = 0; i < 4; i++)
#pragma unroll
            for (int j = 0; j < 4; j++) s[i][j] *= scale;

        if (t == qt) {   // diagonal tile: mask n > m
#pragma unroll
            for (int i = 0; i < 4; i++)
#pragma unroll
                for (int j = 0; j < 4; j++)
                    if (tx * 4 + j > ty * 4 + i) s[i][j] = -1e30f;
        }

        // row max (reduce over 4 local + 16 tx lanes)
        float mt[4];
#pragma unroll
        for (int i = 0; i < 4; i++)
            mt[i] = fmaxf(fmaxf(s[i][0], s[i][1]), fmaxf(s[i][2], s[i][3]));
#pragma unroll
        for (int off = 8; off > 0; off >>= 1)
#pragma unroll
            for (int i = 0; i < 4; i++)
                mt[i] = fmaxf(mt[i], __shfl_xor_sync(0xffffffffu, mt[i], off));

        float mnew[4], corr[4];
#pragma unroll
        for (int i = 0; i < 4; i++) {
            mnew[i] = fmaxf(rm[i], mt[i]);
            corr[i] = expf(rm[i] - mnew[i]);
        }

        float pr[4][4], rs[4];
#pragma unroll
        for (int i = 0; i < 4; i++) {
            rs[i] = 0.0f;
#pragma unroll
            for (int j = 0; j < 4; j++) {
                pr[i][j] = expf(s[i][j] - mnew[i]);
                rs[i] += pr[i][j];
            }
        }
#pragma unroll
        for (int off = 8; off > 0; off >>= 1)
#pragma unroll
            for (int i = 0; i < 4; i++)
                rs[i] += __shfl_xor_sync(0xffffffffu, rs[i], off);

#pragma unroll
        for (int i = 0; i < 4; i++) {
            rl[i] = rl[i] * corr[i] + rs[i];
            rm[i] = mnew[i];
#pragma unroll
            for (int j = 0; j < 8; j++) o[i][j] *= corr[i];
        }

        // stage P transposed: Ps[n][m]
#pragma unroll
        for (int j = 0; j < 4; j++) {
            float4 pv = {pr[0][j], pr[1][j], pr[2][j], pr[3][j]};
            *(float4*)&Ps[(tx * 4 + j) * QPITCH + ty * 4] = pv;
        }
        __syncthreads();

        // O += P @ V (4 q-rows x 8 d-cols per thread)
#pragma unroll 2
        for (int n = 0; n < FBK; n++) {
            float4 pa = *(const float4*)&Ps[n * QPITCH + ty * 4];
            float4 va = *(const float4*)&Vs[n * HD + tx * 4];
            float4 vb = *(const float4*)&Vs[n * HD + 64 + tx * 4];
            float pv[4] = {pa.x, pa.y, pa.z, pa.w};
            float vv[8] = {va.x, va.y, va.z, va.w, vb.x, vb.y, vb.z, vb.w};
#pragma unroll
            for (int i = 0; i < 4; i++)
#pragma unroll
                for (int j = 0; j < 8; j++)
                    o[i][j] = fmaf(pv[i], vv[j], o[i][j]);
        }
    }

    // epilogue: normalize + write [B,S,D] packed heads
    float* Ob = Oout + ((size_t)b * SEQ) * D_MODEL + h * HD;
#pragma unroll
    for (int i = 0; i < 4; i++) {
        float inv = 1.0f / rl[i];
        float4 r0 = {o[i][0] * inv, o[i][1] * inv, o[i][2] * inv, o[i][3] * inv};
        float4 r1 = {o[i][4] * inv, o[i][5] * inv, o[i][6] * inv, o[i][7] * inv};
        float* op = Ob + (size_t)(q0 + ty * 4 + i) * D_MODEL + tx * 4;
        *(float4*)op = r0;
        *(float4*)(op + 64) = r1;
    }
}

// ---------------------------------------------------------------------------
extern "C" void kernel_launch(void* const* d_in, const int* in_sizes, int n_in,
                              void* d_out, int out_size)
{
    const float* x  = (const float*)d_in[0];
    const float* Wq = (const float*)d_in[1];
    const float* Wk = (const float*)d_in[2];
    const float* Wv = (const float*)d_in[3];
    const float* Wo = (const float*)d_in[4];
    // d_in[5] = attn_mask (causal) -- implemented analytically, not read
    float* out = (float*)d_out;

    float *q, *k, *v, *attn;
    cudaGetSymbolAddress((void**)&q, g_q);
    cudaGetSymbolAddress((void**)&k, g_k);
    cudaGetSymbolAddress((void**)&v, g_v);
    cudaGetSymbolAddress((void**)&attn, g_attn);

    const int M = BATCH * SEQ, N = D_MODEL, Kd = D_MODEL;
    dim3 gg(N / 128, M / 128);

    sgemm_nt<<<gg, 256>>>(x, Wq, q, M, N, Kd);
    sgemm_nt<<<gg, 256>>>(x, Wk, k, M, N, Kd);
    sgemm_nt<<<gg, 256>>>(x, Wv, v, M, N, Kd);

    const int pairs = BATCH * SEQ * NHEAD * (HD / 2);
    rope_kernel<<<pairs / 256, 256>>>(q, pairs);
    rope_kernel<<<pairs / 256, 256>>>(k, pairs);

    size_t smem = (size_t)(HD * QPITCH * 2 + FBK * HD + FBK * QPITCH) * sizeof(float);
    cudaFuncSetAttribute(flash_attn, cudaFuncAttributeMaxDynamicSharedMemorySize, (int)smem);
    flash_attn<<<dim3(SEQ / FBQ, BATCH * NHEAD), 256, smem>>>(q, k, v, attn);

    sgemm_nt<<<gg, 256>>>(attn, Wo, out, M, N, Kd);
}

// round 4
// speedup vs baseline: 3.4751x; 3.4751x over previous
#include <cuda_runtime.h>
#include <cuda_bf16.h>
#include <math.h>
#include <stdint.h>

// Problem constants: B=2, S=2048, D=2048, H=16, hd=128
#define SEQ     2048
#define D_MODEL 2048
#define NHEAD   16
#define HD      128
#define BATCH   2
#define MDIM    (BATCH*SEQ)     // 4096
#define NDIM    D_MODEL         // 2048
#define KDIM    D_MODEL         // 2048

// ---------------- scratch (__device__ globals; no allocations allowed) -----
__device__ float g_q[MDIM * D_MODEL];
__device__ float g_k[MDIM * D_MODEL];
__device__ float g_v[MDIM * D_MODEL];
__device__ float g_attn[MDIM * D_MODEL];
__device__ float g_xr[MDIM * KDIM];       // tf32-rounded x
__device__ float g_wq[NDIM * KDIM];
__device__ float g_wk[NDIM * KDIM];
__device__ float g_wv[NDIM * KDIM];
__device__ float g_wo[NDIM * KDIM];

// ---------------- helpers ---------------------------------------------------
__device__ __forceinline__ uint32_t s2u(const void* p) {
    uint32_t a;
    asm("{ .reg .u64 t; cvta.to.shared.u64 t, %1; cvt.u32.u64 %0, t; }" : "=r"(a) : "l"(p));
    return a;
}
__device__ __forceinline__ float tf32rn(float x) {
    uint32_t u;
    asm("cvt.rn.tf32.f32 %0, %1;" : "=r"(u) : "f"(x));
    return __uint_as_float(u);
}
__device__ __forceinline__ void cpa16(uint32_t s, const void* g) {
    asm volatile("cp.async.cg.shared.global [%0], [%1], 16;\n" :: "r"(s), "l"(g));
}
__device__ __forceinline__ void cpcommit() { asm volatile("cp.async.commit_group;\n" ::); }
template<int N> __device__ __forceinline__ void cpwait() {
    asm volatile("cp.async.wait_group %0;\n" :: "n"(N));
}
__device__ __forceinline__ void mma_tf32(float* c, const uint32_t* a, uint32_t b0, uint32_t b1) {
    asm volatile(
        "mma.sync.aligned.m16n8k8.row.col.f32.tf32.tf32.f32 "
        "{%0,%1,%2,%3}, {%4,%5,%6,%7}, {%8,%9}, {%0,%1,%2,%3};"
        : "+f"(c[0]), "+f"(c[1]), "+f"(c[2]), "+f"(c[3])
        : "r"(a[0]), "r"(a[1]), "r"(a[2]), "r"(a[3]), "r"(b0), "r"(b1));
}

// ---------------- tf32 rounding pass ---------------------------------------
__global__ void tf32_round_kernel(const float4* __restrict__ in,
                                  float4* __restrict__ out, int n4) {
    int i = blockIdx.x * blockDim.x + threadIdx.x;
    if (i >= n4) return;
    float4 v = in[i];
    v.x = tf32rn(v.x); v.y = tf32rn(v.y); v.z = tf32rn(v.z); v.w = tf32rn(v.w);
    out[i] = v;
}

// ---------------- mma.sync tf32 GEMM: C[M,N] = A[M,K] @ B[N,K]^T ------------
// 128x128x32 tile, 256 threads (8 warps, 2x4), warp tile 64x32,
// double-buffered cp.async, fused RoPE epilogue (per grid.z via ropeMask).
#define BM 128
#define BN 128
#define BK 32
#define SP 36                      // smem row pitch (floats): 144B, conflict-free
#define TILE_FLOATS (BM * SP)      // per operand per buffer
#define NT (KDIM / BK)             // 64

__global__ __launch_bounds__(256, 2)
void gemm_mma(const float* __restrict__ A,
              const float* __restrict__ Bq, const float* __restrict__ Bk,
              const float* __restrict__ Bv,
              float* __restrict__ Cq, float* __restrict__ Ck,
              float* __restrict__ Cv, int ropeMask)
{
    extern __shared__ float sm[];
    float* As = sm;                       // [2][BM][SP]
    float* Bs = sm + 2 * TILE_FLOATS;     // [2][BN][SP]
    const uint32_t smA = s2u(As), smB = s2u(Bs);

    const float* B = (blockIdx.z == 0) ? Bq : (blockIdx.z == 1) ? Bk : Bv;
    float*       C = (blockIdx.z == 0) ? Cq : (blockIdx.z == 1) ? Ck : Cv;
    const int rope = (ropeMask >> blockIdx.z) & 1;

    const int tid = threadIdx.x;
    const int warp = tid >> 5, lane = tid & 31;
    const int wm = (warp >> 2) * 64;       // warp row offset (2 warp-rows)
    const int wn = (warp & 3) * 32;        // warp col offset (4 warp-cols)
    const int gid = lane >> 2, tig = lane & 3;

    const int brow = blockIdx.y * BM;
    const int bcol = blockIdx.x * BN;
    const float* Ab = A + (size_t)brow * KDIM;
    const float* Bb = B + (size_t)bcol * KDIM;

    float acc[4][4][4];
#pragma unroll
    for (int i = 0; i < 4; i++)
#pragma unroll
        for (int j = 0; j < 4; j++)
#pragma unroll
            for (int r = 0; r < 4; r++) acc[i][j][r] = 0.0f;

    // prefetch tile 0
    {
#pragma unroll
        for (int c = 0; c < 4; c++) {
            int lin = c * 256 + tid;
            int r = lin >> 3, kc = (lin & 7) * 4;
            cpa16(smA + (uint32_t)(r * SP + kc) * 4, Ab + (size_t)r * KDIM + kc);
            cpa16(smB + (uint32_t)(r * SP + kc) * 4, Bb + (size_t)r * KDIM + kc);
        }
        cpcommit();
    }

    for (int t = 0; t < NT; t++) {
        int buf = t & 1;
        if (t + 1 < NT) {
            int nb = (t + 1) & 1;
            const float* Ag = Ab + (size_t)(t + 1) * BK;
            const float* Bg = Bb + (size_t)(t + 1) * BK;
#pragma unroll
            for (int c = 0; c < 4; c++) {
                int lin = c * 256 + tid;
                int r = lin >> 3, kc = (lin & 7) * 4;
                cpa16(smA + (uint32_t)(nb * TILE_FLOATS + r * SP + kc) * 4,
                      Ag + (size_t)r * KDIM + kc);
                cpa16(smB + (uint32_t)(nb * TILE_FLOATS + r * SP + kc) * 4,
                      Bg + (size_t)r * KDIM + kc);
            }
            cpcommit();
            cpwait<1>();
        } else {
            cpwait<0>();
        }
        __syncthreads();

        const float* Ab_s = As + buf * TILE_FLOATS;
        const float* Bb_s = Bs + buf * TILE_FLOATS;
#pragma unroll
        for (int kk = 0; kk < BK; kk += 8) {
            uint32_t afr[4][4];
#pragma unroll
            for (int ma = 0; ma < 4; ma++) {
                int r = wm + ma * 16;
                afr[ma][0] = __float_as_uint(Ab_s[(r + gid) * SP + kk + tig]);
                afr[ma][1] = __float_as_uint(Ab_s[(r + gid + 8) * SP + kk + tig]);
                afr[ma][2] = __float_as_uint(Ab_s[(r + gid) * SP + kk + tig + 4]);
                afr[ma][3] = __float_as_uint(Ab_s[(r + gid + 8) * SP + kk + tig + 4]);
            }
#pragma unroll
            for (int na = 0; na < 4; na++) {
                int cb = wn + na * 8;
                uint32_t b0 = __float_as_uint(Bb_s[(cb + gid) * SP + kk + tig]);
                uint32_t b1 = __float_as_uint(Bb_s[(cb + gid) * SP + kk + tig + 4]);
#pragma unroll
                for (int ma = 0; ma < 4; ma++)
                    mma_tf32(acc[ma][na], afr[ma], b0, b1);
            }
        }
        __syncthreads();
    }

    // ---- epilogue: fused RoPE (adjacent col pair = (c0,c1) / (c2,c3)) ------
    float invf[4];
    if (rope) {
#pragma unroll
        for (int na = 0; na < 4; na++) {
            int p = ((bcol + wn + na * 8 + tig * 2) & 127) >> 1;
            invf[na] = (float)exp(-(double)p * (9.210340371976184 / 64.0));
        }
    }

#pragma unroll
    for (int ma = 0; ma < 4; ma++) {
        int r0 = brow + wm + ma * 16 + gid;
        int r1 = r0 + 8;
#pragma unroll
        for (int na = 0; na < 4; na++) {
            int col = bcol + wn + na * 8 + tig * 2;
            float c0 = acc[ma][na][0], c1 = acc[ma][na][1];
            float c2 = acc[ma][na][2], c3 = acc[ma][na][3];
            if (rope) {
                float sn, cs;
                sincosf((float)(r0 & (SEQ - 1)) * invf[na], &sn, &cs);
                float t0 = c0 * cs - c1 * sn, t1 = c0 * sn + c1 * cs;
                c0 = t0; c1 = t1;
                sincosf((float)(r1 & (SEQ - 1)) * invf[na], &sn, &cs);
                float t2 = c2 * cs - c3 * sn, t3 = c2 * sn + c3 * cs;
                c2 = t2; c3 = t3;
            }
            *(float2*)(C + (size_t)r0 * NDIM + col) = make_float2(c0, c1);
            *(float2*)(C + (size_t)r1 * NDIM + col) = make_float2(c2, c3);
        }
    }
}

// ---------------------------------------------------------------------------
// Flash attention, fp32, causal. BQ=BK=64, hd=128, 256 threads (16x16).
// Output written tf32-rounded (feeds the tf32 O-projection GEMM).
// ---------------------------------------------------------------------------
#define FBQ 64
#define FBK 64
#define QPITCH 68

__global__ __launch_bounds__(256)
void flash_attn(const float* __restrict__ Q, const float* __restrict__ K,
                const float* __restrict__ V, float* __restrict__ Oout)
{
    extern __shared__ float smf[];
    float* Qs = smf;                       // [HD][QPITCH]
    float* Ks = Qs + HD * QPITCH;          // [HD][QPITCH]
    float* Vs = Ks + HD * QPITCH;          // [FBK][HD]
    float* Ps = Vs + FBK * HD;             // [FBK][QPITCH]

    const int qt = blockIdx.x;
    const int bh = blockIdx.y;
    const int b = bh >> 4, h = bh & 15;
    const int q0 = qt * FBQ;
    const int tid = threadIdx.x;
    const int tx = tid & 15, ty = tid >> 4;

    const float* Qb = Q + ((size_t)b * SEQ) * D_MODEL + h * HD;
    const float* Kb = K + ((size_t)b * SEQ) * D_MODEL + h * HD;
    const float* Vb = V + ((size_t)b * SEQ) * D_MODEL + h * HD;

    for (int idx = tid; idx < FBQ * 32; idx += 256) {
        int r = idx >> 5;
        int c4 = (idx & 31) * 4;
        float4 v4 = *(const float4*)(Qb + (size_t)(q0 + r) * D_MODEL + c4);
        Qs[(c4 + 0) * QPITCH + r] = v4.x;
        Qs[(c4 + 1) * QPITCH + r] = v4.y;
        Qs[(c4 + 2) * QPITCH + r] = v4.z;
        Qs[(c4 + 3) * QPITCH + r] = v4.w;
    }

    float o[4][8];
#pragma unroll
    for (int i = 0; i < 4; i++)
#pragma unroll
        for (int j = 0; j < 8; j++) o[i][j] = 0.0f;
    float rm[4], rl[4];
#pragma unroll
    for (int i = 0; i < 4; i++) { rm[i] = -1e30f; rl[i] = 0.0f; }

    const float scale = 0.08838834764831845f;
    const int ntiles = qt + 1;

    for (int t = 0; t < ntiles; t++) {
        int k0 = t * FBK;
        __syncthreads();

        for (int idx = tid; idx < FBK * 32; idx += 256) {
            int r = idx >> 5;
            int c4 = (idx & 31) * 4;
            float4 kv = *(const float4*)(Kb + (size_t)(k0 + r) * D_MODEL + c4);
            Ks[(c4 + 0) * QPITCH + r] = kv.x;
            Ks[(c4 + 1) * QPITCH + r] = kv.y;
            Ks[(c4 + 2) * QPITCH + r] = kv.z;
            Ks[(c4 + 3) * QPITCH + r] = kv.w;
            float4 vv = *(const float4*)(Vb + (size_t)(k0 + r) * D_MODEL + c4);
            *(float4*)&Vs[r * HD + c4] = vv;
        }
        __syncthreads();

        float s[4][4];
#pragma unroll
        for (int i = 0; i < 4; i++)
#pragma unroll
            for (int j = 0; j < 4; j++) s[i][j] = 0.0f;

#pragma unroll 4
        for (int k = 0; k < HD; k++) {
            float4 qa = *(const float4*)&Qs[k * QPITCH + ty * 4];
            float4 ka = *(const float4*)&Ks[k * QPITCH + tx * 4];
            float qv[4] = {qa.x, qa.y, qa.z, qa.w};
            float kv[4] = {ka.x, ka.y, ka.z, ka.w};
#pragma unroll
            for (int i = 0; i < 4; i++)
#pragma unroll
                for (int j = 0; j < 4; j++)
                    s[i][j] = fmaf(qv[i], kv[j], s[i][j]);
        }

#pragma unroll
        for (int i = 0; i < 4; i++)
#pragma unroll
            for (int j = 0; j < 4; j++) s[i][j] *= scale;

        if (t == qt) {
#pragma unroll
            for (int i = 0; i < 4; i++)
#pragma unroll
                for (int j = 0; j < 4; j++)
                    if (tx * 4 + j > ty * 4 + i) s[i][j] = -1e30f;
        }

        float mt[4];
#pragma unroll
        for (int i = 0; i < 4; i++)
            mt[i] = fmaxf(fmaxf(s[i][0], s[i][1]), fmaxf(s[i][2], s[i][3]));
#pragma unroll
        for (int off = 8; off > 0; off >>= 1)
#pragma unroll
            for (int i = 0; i < 4; i++)
                mt[i] = fmaxf(mt[i], __shfl_xor_sync(0xffffffffu, mt[i], off));

        float mnew[4], corr[4];
#pragma unroll
        for (int i = 0; i < 4; i++) {
            mnew[i] = fmaxf(rm[i], mt[i]);
            corr[i] = expf(rm[i] - mnew[i]);
        }

        float pr[4][4], rs[4];
#pragma unroll
        for (int i = 0; i < 4; i++) {
            rs[i] = 0.0f;
#pragma unroll
            for (int j = 0; j < 4; j++) {
                pr[i][j] = expf(s[i][j] - mnew[i]);
                rs[i] += pr[i][j];
            }
        }
#pragma unroll
        for (int off = 8; off > 0; off >>= 1)
#pragma unroll
            for (int i = 0; i < 4; i++)
                rs[i] += __shfl_xor_sync(0xffffffffu, rs[i], off);

#pragma unroll
        for (int i = 0; i < 4; i++) {
            rl[i] = rl[i] * corr[i] + rs[i];
            rm[i] = mnew[i];
#pragma unroll
            for (int j = 0; j < 8; j++) o[i][j] *= corr[i];
        }

#pragma unroll
        for (int j = 0; j < 4; j++) {
            float4 pv = {pr[0][j], pr[1][j], pr[2][j], pr[3][j]};
            *(float4*)&Ps[(tx * 4 + j) * QPITCH + ty * 4] = pv;
        }
        __syncthreads();

#pragma unroll 2
        for (int n = 0; n < FBK; n++) {
            float4 pa = *(const float4*)&Ps[n * QPITCH + ty * 4];
            float4 va = *(const float4*)&Vs[n * HD + tx * 4];
            float4 vb = *(const float4*)&Vs[n * HD + 64 + tx * 4];
            float pv[4] = {pa.x, pa.y, pa.z, pa.w};
            float vv[8] = {va.x, va.y, va.z, va.w, vb.x, vb.y, vb.z, vb.w};
#pragma unroll
            for (int i = 0; i < 4; i++)
#pragma unroll
                for (int j = 0; j < 8; j++)
                    o[i][j] = fmaf(pv[i], vv[j], o[i][j]);
        }
    }

    float* Ob = Oout + ((size_t)b * SEQ) * D_MODEL + h * HD;
#pragma unroll
    for (int i = 0; i < 4; i++) {
        float inv = 1.0f / rl[i];
        float4 r0 = {tf32rn(o[i][0] * inv), tf32rn(o[i][1] * inv),
                     tf32rn(o[i][2] * inv), tf32rn(o[i][3] * inv)};
        float4 r1 = {tf32rn(o[i][4] * inv), tf32rn(o[i][5] * inv),
                     tf32rn(o[i][6] * inv), tf32rn(o[i][7] * inv)};
        float* op = Ob + (size_t)(q0 + ty * 4 + i) * D_MODEL + tx * 4;
        *(float4*)op = r0;
        *(float4*)(op + 64) = r1;
    }
}

// ---------------------------------------------------------------------------
extern "C" void kernel_launch(void* const* d_in, const int* in_sizes, int n_in,
                              void* d_out, int out_size)
{
    const float* x  = (const float*)d_in[0];
    const float* Wq = (const float*)d_in[1];
    const float* Wk = (const float*)d_in[2];
    const float* Wv = (const float*)d_in[3];
    const float* Wo = (const float*)d_in[4];
    float* out = (float*)d_out;

    float *q, *k, *v, *attn, *xr, *wq, *wk, *wv, *wo;
    cudaGetSymbolAddress((void**)&q, g_q);
    cudaGetSymbolAddress((void**)&k, g_k);
    cudaGetSymbolAddress((void**)&v, g_v);
    cudaGetSymbolAddress((void**)&attn, g_attn);
    cudaGetSymbolAddress((void**)&xr, g_xr);
    cudaGetSymbolAddress((void**)&wq, g_wq);
    cudaGetSymbolAddress((void**)&wk, g_wk);
    cudaGetSymbolAddress((void**)&wv, g_wv);
    cudaGetSymbolAddress((void**)&wo, g_wo);

    // tf32-RN rounding passes (zero-mean input error for the tf32 mma GEMMs)
    const int n4x = MDIM * KDIM / 4;
    const int n4w = NDIM * KDIM / 4;
    tf32_round_kernel<<<(n4x + 255) / 256, 256>>>((const float4*)x, (float4*)xr, n4x);
    tf32_round_kernel<<<(n4w + 255) / 256, 256>>>((const float4*)Wq, (float4*)wq, n4w);
    tf32_round_kernel<<<(n4w + 255) / 256, 256>>>((const float4*)Wk, (float4*)wk, n4w);
    tf32_round_kernel<<<(n4w + 255) / 256, 256>>>((const float4*)Wv, (float4*)wv, n4w);
    tf32_round_kernel<<<(n4w + 255) / 256, 256>>>((const float4*)Wo, (float4*)wo, n4w);

    const int gsmem = 4 * TILE_FLOATS * sizeof(float);   // 73728 B
    cudaFuncSetAttribute(gemm_mma, cudaFuncAttributeMaxDynamicSharedMemorySize, gsmem);

    // Fused QKV projection (+RoPE on q,k in register epilogue)
    gemm_mma<<<dim3(NDIM / BN, MDIM / BM, 3), 256, gsmem>>>(
        xr, wq, wk, wv, q, k, v, 0b011);

    size_t fsm = (size_t)(HD * QPITCH * 2 + FBK * HD + FBK * QPITCH) * sizeof(float);
    cudaFuncSetAttribute(flash_attn, cudaFuncAttributeMaxDynamicSharedMemorySize, (int)fsm);
    flash_attn<<<dim3(SEQ / FBQ, BATCH * NHEAD), 256, fsm>>>(q, k, v, attn);

    // Output projection
    gemm_mma<<<dim3(NDIM / BN, MDIM / BM, 1), 256, gsmem>>>(
        attn, wo, wo, wo, out, out, out, 0);
}

// round 17
// speedup vs baseline: 7.0590x; 2.0313x over previous
#include <cuda_runtime.h>
#include <cuda_bf16.h>
#include <math.h>
#include <stdint.h>

// Problem constants: B=2, S=2048, D=2048, H=16, hd=128
#define SEQ     2048
#define D_MODEL 2048
#define NHEAD   16
#define HD      128
#define BATCH   2
#define MDIM    (BATCH*SEQ)     // 4096
#define NDIM    D_MODEL         // 2048
#define KDIM    D_MODEL         // 2048

// ---------------- scratch (__device__ globals; no allocations allowed) -----
__device__ float g_q[MDIM * D_MODEL];
__device__ float g_k[MDIM * D_MODEL];
__device__ float g_v[MDIM * D_MODEL];
__device__ float g_attn[MDIM * D_MODEL];
__device__ float g_xr[MDIM * KDIM];
__device__ float g_wq[NDIM * KDIM];
__device__ float g_wk[NDIM * KDIM];
__device__ float g_wv[NDIM * KDIM];
__device__ float g_wo[NDIM * KDIM];

// ---------------- helpers ---------------------------------------------------
__device__ __forceinline__ uint32_t s2u(const void* p) {
    uint32_t a;
    asm("{ .reg .u64 t; cvta.to.shared.u64 t, %1; cvt.u32.u64 %0, t; }" : "=r"(a) : "l"(p));
    return a;
}
__device__ __forceinline__ float tf32rn(float x) {
    uint32_t u;
    asm("cvt.rn.tf32.f32 %0, %1;" : "=r"(u) : "f"(x));
    return __uint_as_float(u);
}
__device__ __forceinline__ void cpa16(uint32_t s, const void* g) {
    asm volatile("cp.async.cg.shared.global [%0], [%1], 16;\n" :: "r"(s), "l"(g));
}
__device__ __forceinline__ void cpcommit() { asm volatile("cp.async.commit_group;\n" ::); }
template<int N> __device__ __forceinline__ void cpwait() {
    asm volatile("cp.async.wait_group %0;\n" :: "n"(N));
}
__device__ __forceinline__ void mma_tf32(float* c, const uint32_t* a, uint32_t b0, uint32_t b1) {
    asm volatile(
        "mma.sync.aligned.m16n8k8.row.col.f32.tf32.tf32.f32 "
        "{%0,%1,%2,%3}, {%4,%5,%6,%7}, {%8,%9}, {%0,%1,%2,%3};"
        : "+f"(c[0]), "+f"(c[1]), "+f"(c[2]), "+f"(c[3])
        : "r"(a[0]), "r"(a[1]), "r"(a[2]), "r"(a[3]), "r"(b0), "r"(b1));
}

// ---------------- tf32 rounding pass ---------------------------------------
__global__ void tf32_round_kernel(const float4* __restrict__ in,
                                  float4* __restrict__ out, int n4) {
    int i = blockIdx.x * blockDim.x + threadIdx.x;
    if (i >= n4) return;
    float4 v = in[i];
    v.x = tf32rn(v.x); v.y = tf32rn(v.y); v.z = tf32rn(v.z); v.w = tf32rn(v.w);
    out[i] = v;
}

// ---------------- mma.sync tf32 GEMM: C[M,N] = A[M,K] @ B[N,K]^T ------------
#define BM 128
#define BN 128
#define BK 32
#define SP 36
#define TILE_FLOATS (BM * SP)
#define NT (KDIM / BK)

__global__ __launch_bounds__(256, 2)
void gemm_mma(const float* __restrict__ A,
              const float* __restrict__ Bq, const float* __restrict__ Bk,
              const float* __restrict__ Bv,
              float* __restrict__ Cq, float* __restrict__ Ck,
              float* __restrict__ Cv, int ropeMask, int roundMask)
{
    extern __shared__ float sm[];
    float* As = sm;
    float* Bs = sm + 2 * TILE_FLOATS;
    const uint32_t smA = s2u(As), smB = s2u(Bs);

    const float* B = (blockIdx.z == 0) ? Bq : (blockIdx.z == 1) ? Bk : Bv;
    float*       C = (blockIdx.z == 0) ? Cq : (blockIdx.z == 1) ? Ck : Cv;
    const int rope  = (ropeMask  >> blockIdx.z) & 1;
    const int rnd   = (roundMask >> blockIdx.z) & 1;

    const int tid = threadIdx.x;
    const int warp = tid >> 5, lane = tid & 31;
    const int wm = (warp >> 2) * 64;
    const int wn = (warp & 3) * 32;
    const int gid = lane >> 2, tig = lane & 3;

    const int brow = blockIdx.y * BM;
    const int bcol = blockIdx.x * BN;
    const float* Ab = A + (size_t)brow * KDIM;
    const float* Bb = B + (size_t)bcol * KDIM;

    float acc[4][4][4];
#pragma unroll
    for (int i = 0; i < 4; i++)
#pragma unroll
        for (int j = 0; j < 4; j++)
#pragma unroll
            for (int r = 0; r < 4; r++) acc[i][j][r] = 0.0f;

    {
#pragma unroll
        for (int c = 0; c < 4; c++) {
            int lin = c * 256 + tid;
            int r = lin >> 3, kc = (lin & 7) * 4;
            cpa16(smA + (uint32_t)(r * SP + kc) * 4, Ab + (size_t)r * KDIM + kc);
            cpa16(smB + (uint32_t)(r * SP + kc) * 4, Bb + (size_t)r * KDIM + kc);
        }
        cpcommit();
    }

    for (int t = 0; t < NT; t++) {
        int buf = t & 1;
        if (t + 1 < NT) {
            int nb = (t + 1) & 1;
            const float* Ag = Ab + (size_t)(t + 1) * BK;
            const float* Bg = Bb + (size_t)(t + 1) * BK;
#pragma unroll
            for (int c = 0; c < 4; c++) {
                int lin = c * 256 + tid;
                int r = lin >> 3, kc = (lin & 7) * 4;
                cpa16(smA + (uint32_t)(nb * TILE_FLOATS + r * SP + kc) * 4,
                      Ag + (size_t)r * KDIM + kc);
                cpa16(smB + (uint32_t)(nb * TILE_FLOATS + r * SP + kc) * 4,
                      Bg + (size_t)r * KDIM + kc);
            }
            cpcommit();
            cpwait<1>();
        } else {
            cpwait<0>();
        }
        __syncthreads();

        const float* Ab_s = As + buf * TILE_FLOATS;
        const float* Bb_s = Bs + buf * TILE_FLOATS;
#pragma unroll
        for (int kk = 0; kk < BK; kk += 8) {
            uint32_t afr[4][4];
#pragma unroll
            for (int ma = 0; ma < 4; ma++) {
                int r = wm + ma * 16;
                afr[ma][0] = __float_as_uint(Ab_s[(r + gid) * SP + kk + tig]);
                afr[ma][1] = __float_as_uint(Ab_s[(r + gid + 8) * SP + kk + tig]);
                afr[ma][2] = __float_as_uint(Ab_s[(r + gid) * SP + kk + tig + 4]);
                afr[ma][3] = __float_as_uint(Ab_s[(r + gid + 8) * SP + kk + tig + 4]);
            }
#pragma unroll
            for (int na = 0; na < 4; na++) {
                int cb = wn + na * 8;
                uint32_t b0 = __float_as_uint(Bb_s[(cb + gid) * SP + kk + tig]);
                uint32_t b1 = __float_as_uint(Bb_s[(cb + gid) * SP + kk + tig + 4]);
#pragma unroll
                for (int ma = 0; ma < 4; ma++)
                    mma_tf32(acc[ma][na], afr[ma], b0, b1);
            }
        }
        __syncthreads();
    }

    // ---- epilogue: fused RoPE + optional tf32 rounding ----------------------
    float invf[4];
    if (rope) {
#pragma unroll
        for (int na = 0; na < 4; na++) {
            int p = ((bcol + wn + na * 8 + tig * 2) & 127) >> 1;
            invf[na] = (float)exp(-(double)p * (9.210340371976184 / 64.0));
        }
    }

#pragma unroll
    for (int ma = 0; ma < 4; ma++) {
        int r0 = brow + wm + ma * 16 + gid;
        int r1 = r0 + 8;
#pragma unroll
        for (int na = 0; na < 4; na++) {
            int col = bcol + wn + na * 8 + tig * 2;
            float c0 = acc[ma][na][0], c1 = acc[ma][na][1];
            float c2 = acc[ma][na][2], c3 = acc[ma][na][3];
            if (rope) {
                float sn, cs;
                sincosf((float)(r0 & (SEQ - 1)) * invf[na], &sn, &cs);
                float t0 = c0 * cs - c1 * sn, t1 = c0 * sn + c1 * cs;
                c0 = t0; c1 = t1;
                sincosf((float)(r1 & (SEQ - 1)) * invf[na], &sn, &cs);
                float t2 = c2 * cs - c3 * sn, t3 = c2 * sn + c3 * cs;
                c2 = t2; c3 = t3;
            }
            if (rnd) {
                c0 = tf32rn(c0); c1 = tf32rn(c1);
                c2 = tf32rn(c2); c3 = tf32rn(c3);
            }
            *(float2*)(C + (size_t)r0 * NDIM + col) = make_float2(c0, c1);
            *(float2*)(C + (size_t)r1 * NDIM + col) = make_float2(c2, c3);
        }
    }
}

// ---------------------------------------------------------------------------
// Flash attention on tensor cores (tf32 mma), causal, online softmax.
// BQ=128, BK=64, 8 warps (one m16 row-slab each). K double-buffered,
// V single-buffered cp.async. Inputs q/k/v are tf32-pre-rounded.
// ---------------------------------------------------------------------------
#define ABQ 128
#define ABK 64
#define QP  132    // Q smem pitch (floats) -> conflict-free fragment loads
#define KP  132
#define VP  136
#define PP  76
#define FQTILES (SEQ / ABQ)   // 16

#define FLASH_SMEM ((ABQ*QP + 2*ABK*KP + ABK*VP + ABQ*PP) * 4)

__global__ __launch_bounds__(256, 1)
void flash_mma(const float* __restrict__ Q, const float* __restrict__ K,
               const float* __restrict__ V, float* __restrict__ Oout)
{
    extern __shared__ float sm[];
    float* Qs = sm;                       // [128][QP]
    float* Ks = Qs + ABQ * QP;            // [2][64][KP]
    float* Vs = Ks + 2 * ABK * KP;        // [64][VP]
    float* Ps = Vs + ABK * VP;            // [128][PP]
    const uint32_t smK = s2u(Ks), smV = s2u(Vs);

    const int qt = (FQTILES - 1) - blockIdx.x;        // LPT order
    const int bh = blockIdx.y;
    const int b = bh >> 4, h = bh & 15;
    const int q0 = qt * ABQ;
    const int tid = threadIdx.x;
    const int warp = tid >> 5, lane = tid & 31;
    const int gid = lane >> 2, tig = lane & 3;
    const int wm = warp * 16;

    const float* Qb = Q + ((size_t)b * SEQ) * D_MODEL + h * HD;
    const float* Kb = K + ((size_t)b * SEQ) * D_MODEL + h * HD;
    const float* Vb = V + ((size_t)b * SEQ) * D_MODEL + h * HD;

    // load Q tile [128][128] (pitched copy)
    for (int idx = tid; idx < ABQ * 32; idx += 256) {
        int r = idx >> 5, c4 = (idx & 31) * 4;
        float4 v4 = *(const float4*)(Qb + (size_t)(q0 + r) * D_MODEL + c4);
        Qs[r * QP + c4 + 0] = v4.x;
        Qs[r * QP + c4 + 1] = v4.y;
        Qs[r * QP + c4 + 2] = v4.z;
        Qs[r * QP + c4 + 3] = v4.w;
    }

    float o[16][4];
#pragma unroll
    for (int d = 0; d < 16; d++)
#pragma unroll
        for (int r = 0; r < 4; r++) o[d][r] = 0.0f;
    float rm0 = -1e30f, rm1 = -1e30f, rl0 = 0.0f, rl1 = 0.0f;

    const float scale = 0.08838834764831845f;   // 1/sqrt(128)
    const int nt = 2 * qt + 2;

    // prologue: K0
    {
#pragma unroll
        for (int i = 0; i < 8; i++) {
            int lin = i * 256 + tid;
            int r = lin >> 5, c4 = (lin & 31) * 4;
            cpa16(smK + (uint32_t)(r * KP + c4) * 4, Kb + (size_t)r * D_MODEL + c4);
        }
        cpcommit();
    }

    for (int t = 0; t < nt; t++) {
        const int n0 = t * ABK;
        // issue V_t
#pragma unroll
        for (int i = 0; i < 8; i++) {
            int lin = i * 256 + tid;
            int r = lin >> 5, c4 = (lin & 31) * 4;
            cpa16(smV + (uint32_t)(r * VP + c4) * 4,
                  Vb + (size_t)(n0 + r) * D_MODEL + c4);
        }
        cpcommit();

        cpwait<1>();             // K_t complete
        __syncthreads();

        // ---- S = Q K^T (warp slab: 16 x 64) ----
        const float* Kbuf = Ks + (t & 1) * ABK * KP;
        float s[8][4];
#pragma unroll
        for (int nb = 0; nb < 8; nb++)
#pragma unroll
            for (int r = 0; r < 4; r++) s[nb][r] = 0.0f;

#pragma unroll
        for (int kk = 0; kk < HD; kk += 8) {
            uint32_t afr[4];
            afr[0] = __float_as_uint(Qs[(wm + gid) * QP + kk + tig]);
            afr[1] = __float_as_uint(Qs[(wm + gid + 8) * QP + kk + tig]);
            afr[2] = __float_as_uint(Qs[(wm + gid) * QP + kk + tig + 4]);
            afr[3] = __float_as_uint(Qs[(wm + gid + 8) * QP + kk + tig + 4]);
#pragma unroll
            for (int nb = 0; nb < 8; nb++) {
                uint32_t b0 = __float_as_uint(Kbuf[(nb * 8 + gid) * KP + kk + tig]);
                uint32_t b1 = __float_as_uint(Kbuf[(nb * 8 + gid) * KP + kk + tig + 4]);
                mma_tf32(s[nb], afr, b0, b1);
            }
        }

        // prefetch K_{t+1}
        if (t + 1 < nt) {
            uint32_t kb = smK + (uint32_t)(((t + 1) & 1) * ABK * KP) * 4;
#pragma unroll
            for (int i = 0; i < 8; i++) {
                int lin = i * 256 + tid;
                int r = lin >> 5, c4 = (lin & 31) * 4;
                cpa16(kb + (uint32_t)(r * KP + c4) * 4,
                      Kb + (size_t)(n0 + ABK + r) * D_MODEL + c4);
            }
            cpcommit();
        }

        // ---- softmax on fragments ----
#pragma unroll
        for (int nb = 0; nb < 8; nb++)
#pragma unroll
            for (int r = 0; r < 4; r++) s[nb][r] *= scale;

        if (n0 + 63 > q0 + wm) {     // diagonal-crossing tile for this warp
            int grow0 = q0 + wm + gid, grow1 = grow0 + 8;
#pragma unroll
            for (int nb = 0; nb < 8; nb++) {
                int gc = n0 + nb * 8 + tig * 2;
                if (gc > grow0)     s[nb][0] = -1e30f;
                if (gc + 1 > grow0) s[nb][1] = -1e30f;
                if (gc > grow1)     s[nb][2] = -1e30f;
                if (gc + 1 > grow1) s[nb][3] = -1e30f;
            }
        }

        float mt0 = -1e30f, mt1 = -1e30f;
#pragma unroll
        for (int nb = 0; nb < 8; nb++) {
            mt0 = fmaxf(mt0, fmaxf(s[nb][0], s[nb][1]));
            mt1 = fmaxf(mt1, fmaxf(s[nb][2], s[nb][3]));
        }
        mt0 = fmaxf(mt0, __shfl_xor_sync(0xffffffffu, mt0, 1));
        mt0 = fmaxf(mt0, __shfl_xor_sync(0xffffffffu, mt0, 2));
        mt1 = fmaxf(mt1, __shfl_xor_sync(0xffffffffu, mt1, 1));
        mt1 = fmaxf(mt1, __shfl_xor_sync(0xffffffffu, mt1, 2));

        float mn0 = fmaxf(rm0, mt0), mn1 = fmaxf(rm1, mt1);
        float cr0 = __expf(rm0 - mn0), cr1 = __expf(rm1 - mn1);

        float sum0 = 0.0f, sum1 = 0.0f;
#pragma unroll
        for (int nb = 0; nb < 8; nb++) {
            s[nb][0] = __expf(s[nb][0] - mn0);
            s[nb][1] = __expf(s[nb][1] - mn0);
            s[nb][2] = __expf(s[nb][2] - mn1);
            s[nb][3] = __expf(s[nb][3] - mn1);
            sum0 += s[nb][0] + s[nb][1];
            sum1 += s[nb][2] + s[nb][3];
        }
        sum0 += __shfl_xor_sync(0xffffffffu, sum0, 1);
        sum0 += __shfl_xor_sync(0xffffffffu, sum0, 2);
        sum1 += __shfl_xor_sync(0xffffffffu, sum1, 1);
        sum1 += __shfl_xor_sync(0xffffffffu, sum1, 2);

        rl0 = rl0 * cr0 + sum0;  rm0 = mn0;
        rl1 = rl1 * cr1 + sum1;  rm1 = mn1;

#pragma unroll
        for (int d = 0; d < 16; d++) {
            o[d][0] *= cr0; o[d][1] *= cr0;
            o[d][2] *= cr1; o[d][3] *= cr1;
        }

        // stage P (tf32-rounded) into warp-private smem region
#pragma unroll
        for (int nb = 0; nb < 8; nb++) {
            *(float2*)&Ps[(wm + gid) * PP + nb * 8 + tig * 2] =
                make_float2(tf32rn(s[nb][0]), tf32rn(s[nb][1]));
            *(float2*)&Ps[(wm + gid + 8) * PP + nb * 8 + tig * 2] =
                make_float2(tf32rn(s[nb][2]), tf32rn(s[nb][3]));
        }

        if (t + 1 < nt) cpwait<1>(); else cpwait<0>();   // V_t complete
        __syncthreads();

        // ---- O += P V (warp slab: 16 x 128) ----
#pragma unroll
        for (int kk = 0; kk < ABK; kk += 8) {
            uint32_t pa[4];
            pa[0] = __float_as_uint(Ps[(wm + gid) * PP + kk + tig]);
            pa[1] = __float_as_uint(Ps[(wm + gid + 8) * PP + kk + tig]);
            pa[2] = __float_as_uint(Ps[(wm + gid) * PP + kk + tig + 4]);
            pa[3] = __float_as_uint(Ps[(wm + gid + 8) * PP + kk + tig + 4]);
#pragma unroll
            for (int db = 0; db < 16; db++) {
                uint32_t b0 = __float_as_uint(Vs[(kk + tig) * VP + db * 8 + gid]);
                uint32_t b1 = __float_as_uint(Vs[(kk + tig + 4) * VP + db * 8 + gid]);
                mma_tf32(o[db], pa, b0, b1);
            }
        }
        __syncthreads();   // Vs/Ks(t&1) consumed; safe for next iteration's fills
    }

    // ---- epilogue: normalize, tf32-round (feeds O-proj GEMM), store --------
    float inv0 = 1.0f / rl0, inv1 = 1.0f / rl1;
    float* Ob = Oout + ((size_t)b * SEQ) * D_MODEL + h * HD;
    int r0 = q0 + wm + gid, r1 = r0 + 8;
#pragma unroll
    for (int db = 0; db < 16; db++) {
        int col = db * 8 + tig * 2;
        *(float2*)(Ob + (size_t)r0 * D_MODEL + col) =
            make_float2(tf32rn(o[db][0] * inv0), tf32rn(o[db][1] * inv0));
        *(float2*)(Ob + (size_t)r1 * D_MODEL + col) =
            make_float2(tf32rn(o[db][2] * inv1), tf32rn(o[db][3] * inv1));
    }
}

// ---------------------------------------------------------------------------
extern "C" void kernel_launch(void* const* d_in, const int* in_sizes, int n_in,
                              void* d_out, int out_size)
{
    const float* x  = (const float*)d_in[0];
    const float* Wq = (const float*)d_in[1];
    const float* Wk = (const float*)d_in[2];
    const float* Wv = (const float*)d_in[3];
    const float* Wo = (const float*)d_in[4];
    float* out = (float*)d_out;

    float *q, *k, *v, *attn, *xr, *wq, *wk, *wv, *wo;
    cudaGetSymbolAddress((void**)&q, g_q);
    cudaGetSymbolAddress((void**)&k, g_k);
    cudaGetSymbolAddress((void**)&v, g_v);
    cudaGetSymbolAddress((void**)&attn, g_attn);
    cudaGetSymbolAddress((void**)&xr, g_xr);
    cudaGetSymbolAddress((void**)&wq, g_wq);
    cudaGetSymbolAddress((void**)&wk, g_wk);
    cudaGetSymbolAddress((void**)&wv, g_wv);
    cudaGetSymbolAddress((void**)&wo, g_wo);

    const int n4x = MDIM * KDIM / 4;
    const int n4w = NDIM * KDIM / 4;
    tf32_round_kernel<<<(n4x + 255) / 256, 256>>>((const float4*)x, (float4*)xr, n4x);
    tf32_round_kernel<<<(n4w + 255) / 256, 256>>>((const float4*)Wq, (float4*)wq, n4w);
    tf32_round_kernel<<<(n4w + 255) / 256, 256>>>((const float4*)Wk, (float4*)wk, n4w);
    tf32_round_kernel<<<(n4w + 255) / 256, 256>>>((const float4*)Wv, (float4*)wv, n4w);
    tf32_round_kernel<<<(n4w + 255) / 256, 256>>>((const float4*)Wo, (float4*)wo, n4w);

    const int gsmem = 4 * TILE_FLOATS * sizeof(float);
    cudaFuncSetAttribute(gemm_mma, cudaFuncAttributeMaxDynamicSharedMemorySize, gsmem);

    // QKV projection: RoPE on q,k; tf32-round all three outputs for flash
    gemm_mma<<<dim3(NDIM / BN, MDIM / BM, 3), 256, gsmem>>>(
        xr, wq, wk, wv, q, k, v, 0b011, 0b111);

    cudaFuncSetAttribute(flash_mma, cudaFuncAttributeMaxDynamicSharedMemorySize, FLASH_SMEM);
    flash_mma<<<dim3(FQTILES, BATCH * NHEAD), 256, FLASH_SMEM>>>(q, k, v, attn);

    // Output projection (no rope, no rounding of final result)
    gemm_mma<<<dim3(NDIM / BN, MDIM / BM, 1), 256, gsmem>>>(
        attn, wo, wo, wo, out, out, out, 0, 0);
}